// round 4
// baseline (speedup 1.0000x reference)
#include <cuda_runtime.h>
#include <cuda_bf16.h>

// Problem constants (from reference)
#define T_DIM 64
#define S_DIM 512
#define X_DIM 16
#define Y_DIM 16
#define G_DIM 64
#define NBLK 32
// MAX_CX = MAX_CY = LAM = 1.0

// Key algebraic facts exploited:
//  * Phi = trans @ V_pre with V_pre == 0  =>  Phi == 0, trans is never read.
//  * J = pi_0 @ V[0]  => only t = 0 matters.
//  * sum_x px[x]*(x+y) = mx + y  with mx = E_px[x].
// So: J = sum_s pi0[s] * sum_y w[s,y] * (A[s,y] + mx + y)
//   w[s,y] = sum_g py[y,g]*obv[s,g],  A[s,y] = sum_x px[x]*loss[s,x,y]

__device__ float g_partial[NBLK];
__device__ unsigned int g_ticket;   // zero-initialized; self-resetting each launch

__global__ void __launch_bounds__(256, 1)
v0_kernel(const float* __restrict__ policy_var,
          const float* __restrict__ obv,
          const float* __restrict__ loss_table,
          const float* __restrict__ pi0,
          float* __restrict__ out)
{
    __shared__ float s_px[X_DIM];
    __shared__ float s_py[Y_DIM][G_DIM];
    __shared__ float s_mx;
    __shared__ float s_red[16];
    __shared__ bool  s_last;

    const int tid = threadIdx.x;

    // ---- px = softmax(policy_var[0:16]) (t = 0 row), plus mx = E_px[x] ----
    if (tid == 0) {
        float v[X_DIM];
        float m = -1e30f;
        #pragma unroll
        for (int x = 0; x < X_DIM; x++) { v[x] = policy_var[x]; m = fmaxf(m, v[x]); }
        float sum = 0.f;
        #pragma unroll
        for (int x = 0; x < X_DIM; x++) { v[x] = expf(v[x] - m); sum += v[x]; }
        const float inv = 1.f / sum;
        float mx = 0.f;
        #pragma unroll
        for (int x = 0; x < X_DIM; x++) {
            const float p = v[x] * inv;
            s_px[x] = p;
            mx += p * (float)x;
        }
        s_mx = mx;
    }

    // ---- py[y,g] = softmax over y of policy_var[T*X + y*G + g] (t = 0) ----
    if (tid < G_DIM) {
        const int g = tid;
        float v[Y_DIM];
        float m = -1e30f;
        #pragma unroll
        for (int y = 0; y < Y_DIM; y++) {
            v[y] = policy_var[T_DIM * X_DIM + y * G_DIM + g];
            m = fmaxf(m, v[y]);
        }
        float sum = 0.f;
        #pragma unroll
        for (int y = 0; y < Y_DIM; y++) { v[y] = expf(v[y] - m); sum += v[y]; }
        const float inv = 1.f / sum;
        #pragma unroll
        for (int y = 0; y < Y_DIM; y++) s_py[y][g] = v[y] * inv;
    }
    __syncthreads();

    // ---- each block: 16 s values; thread = (s_local, y) ----
    const int si = tid >> 4;     // 0..15
    const int y  = tid & 15;     // 0..15
    const int s  = blockIdx.x * 16 + si;

    // w = sum_g py[y,g] * obv[s,g]
    const float* __restrict__ obv_s = obv + s * G_DIM;
    float w = 0.f;
    #pragma unroll 8
    for (int g = 0; g < G_DIM; g++) w = fmaf(s_py[y][g], obv_s[g], w);

    // A = sum_x px[x] * loss[s,x,y]   (stride-16 per thread; warp covers
    // contiguous 64 floats per x -> fully coalesced 128B sectors)
    const float* __restrict__ ls = loss_table + s * (X_DIM * Y_DIM) + y;
    float A = 0.f;
    #pragma unroll
    for (int x = 0; x < X_DIM; x++) A = fmaf(s_px[x], ls[x * Y_DIM], A);

    float val = w * (A + s_mx + (float)y);

    // reduce over the 16 y-lanes (xor offsets <= 8 stay inside each 16-lane group)
    #pragma unroll
    for (int off = 8; off >= 1; off >>= 1)
        val += __shfl_xor_sync(0xFFFFFFFFu, val, off);

    if ((tid & 15) == 0) s_red[si] = val * pi0[s];
    __syncthreads();

    if (tid == 0) {
        float total = 0.f;
        #pragma unroll
        for (int i = 0; i < 16; i++) total += s_red[i];
        g_partial[blockIdx.x] = total;
        __threadfence();                       // release partial before ticket
        unsigned int t = atomicAdd(&g_ticket, 1u);
        s_last = (t == NBLK - 1);
    }
    __syncthreads();

    // Last block to finish performs the deterministic final reduction.
    if (s_last && tid == 0) {
        const volatile float* vp = g_partial;  // acquire side: force L2 reads
        float total = 0.f;
        #pragma unroll
        for (int i = 0; i < NBLK; i++) total += vp[i];
        out[0] = total;
        g_ticket = 0u;   // self-reset for the next (graph-replayed) launch
    }
}

extern "C" void kernel_launch(void* const* d_in, const int* in_sizes, int n_in,
                              void* d_out, int out_size)
{
    // metadata order: policy_var, trans, obv, loss_table, pi_0
    const float* policy_var = (const float*)d_in[0];
    // const float* trans   = (const float*)d_in[1];   // provably unused: Phi == 0
    const float* obv        = (const float*)d_in[2];
    const float* loss_table = (const float*)d_in[3];
    const float* pi0        = (const float*)d_in[4];
    float* out = (float*)d_out;

    v0_kernel<<<NBLK, 256>>>(policy_var, obv, loss_table, pi0, out);
}